// round 14
// baseline (speedup 1.0000x reference)
#include <cuda_runtime.h>
#include <cuda_fp16.h>
#include <cstdint>

// ---------------------------------------------------------------------------
// Problem constants
// ---------------------------------------------------------------------------
#define N_IMG   16
#define C_IN    64
#define C_OUT   64
#define HH      128
#define WW      128
#define W_ELEMS (C_OUT * C_IN * 9)      // 36864
#define HP      130                      // padded H/W
#define XP_ELEMS (N_IMG * HP * HP * 64)  // fp16 padded NHWC scratch

// ---------------------------------------------------------------------------
// Persistent device scratch (zero-initialized; g_xp borders stay 0 forever)
// ---------------------------------------------------------------------------
__device__ double  g_part[32];
__device__ __half  g_xp[XP_ELEMS];        // [n][h+1][w+1][c]
__device__ __half  g_wB[9 * 64 * 64];     // [tap][oc][c]
__device__ float   g_beff[C_OUT];

// ---------------------------------------------------------------------------
// PTX helpers (sm_103-baseline: cp.async, ldmatrix, mma.sync)
// ---------------------------------------------------------------------------
__device__ __forceinline__ uint32_t smem_to_u32(const void* p) {
    uint32_t a;
    asm("{ .reg .u64 t; cvta.to.shared.u64 t, %1; cvt.u32.u64 %0, t; }"
        : "=r"(a) : "l"(p));
    return a;
}
__device__ __forceinline__ void cp16(uint32_t dst, const void* src) {
    asm volatile("cp.async.cg.shared.global [%0], [%1], 16;" :: "r"(dst), "l"(src));
}
__device__ __forceinline__ void cp_commit() {
    asm volatile("cp.async.commit_group;" ::: "memory");
}
__device__ __forceinline__ void cp_wait0() {
    asm volatile("cp.async.wait_group 0;" ::: "memory");
}
__device__ __forceinline__ void ldsm_x4(uint32_t* r, uint32_t addr) {
    asm volatile("ldmatrix.sync.aligned.m8n8.x4.shared.b16 {%0,%1,%2,%3}, [%4];"
        : "=r"(r[0]), "=r"(r[1]), "=r"(r[2]), "=r"(r[3]) : "r"(addr));
}
__device__ __forceinline__ void mma16816(float* d, const uint32_t* a, const uint32_t* b) {
    asm volatile(
        "mma.sync.aligned.m16n8k16.row.col.f32.f16.f16.f32 "
        "{%0,%1,%2,%3}, {%4,%5,%6,%7}, {%8,%9}, {%0,%1,%2,%3};"
        : "+f"(d[0]), "+f"(d[1]), "+f"(d[2]), "+f"(d[3])
        : "r"(a[0]), "r"(a[1]), "r"(a[2]), "r"(a[3]), "r"(b[0]), "r"(b[1]));
}
// evict-first streaming load (x is single-use)
__device__ __forceinline__ float4 ldg_cs_f4(const float* p) {
    float4 v;
    asm volatile("ld.global.cs.v4.f32 {%0,%1,%2,%3}, [%4];"
        : "=f"(v.x), "=f"(v.y), "=f"(v.z), "=f"(v.w) : "l"(p));
    return v;
}

// ---------------------------------------------------------------------------
// Kernel 1: fused  (blocks 0..31: fp64 |w| partial sums)
//   (blocks 32..: NCHW fp32 -> padded NHWC fp16 transpose — proven version)
// ---------------------------------------------------------------------------
__global__ __launch_bounds__(256)
void transpose_scale_kernel(const float* __restrict__ x,
                            const float* __restrict__ w,
                            const float* __restrict__ wc) {
    const int tid = threadIdx.x;
    if (blockIdx.x < 32) {
        int b = blockIdx.x;
        const float* p = (b < 16) ? w : wc;
        int seg = b & 15;
        int start = seg * (W_ELEMS / 16);
        double s = 0.0;
        for (int i = start + tid; i < start + W_ELEMS / 16; i += 256)
            s += (double)fabsf(p[i]);
        __shared__ double red[256];
        red[tid] = s;
        __syncthreads();
        for (int off = 128; off > 0; off >>= 1) {
            if (tid < off) red[tid] += red[tid + off];
            __syncthreads();
        }
        if (tid == 0) g_part[b] = red[0];
        return;
    }

    const int idx = blockIdx.x - 32;
    const int w0 = (idx & 3) * 32;
    const int h  = (idx >> 2) & 127;
    const int n  = idx >> 9;

    __shared__ float s[32 * 65];
#pragma unroll
    for (int it = 0; it < 2; ++it) {
        int i = tid + it * 256;            // 0..511 = 64ch x 8 chunks
        int c = i >> 3, j = i & 7;
        float4 v = ldg_cs_f4(
            x + (((size_t)(n * 64 + c)) * HH + h) * WW + w0 + j * 4);
        int wb = j * 4;
        s[(wb + 0) * 65 + c] = v.x;
        s[(wb + 1) * 65 + c] = v.y;
        s[(wb + 2) * 65 + c] = v.z;
        s[(wb + 3) * 65 + c] = v.w;
    }
    __syncthreads();

    int wcx = tid >> 3;
    int cg = (tid & 7) * 8;
    alignas(16) __half h8[8];
#pragma unroll
    for (int j = 0; j < 8; ++j)
        h8[j] = __float2half_rn(s[wcx * 65 + cg + j]);
    size_t dst = (((size_t)n * HP + (h + 1)) * HP + (w0 + wcx + 1)) * 64 + cg;
    *reinterpret_cast<uint4*>(&g_xp[dst]) = *reinterpret_cast<const uint4*>(h8);
}

// ---------------------------------------------------------------------------
// Kernel 2: finalize scales (redundant per block) + fuse ternary weights
// ---------------------------------------------------------------------------
__global__ void prep_kernel(const float* __restrict__ w,
                            const float* __restrict__ b,
                            const float* __restrict__ wc,
                            const float* __restrict__ bc,
                            const float* __restrict__ gate) {
    __shared__ float ssc[2];
    if (threadIdx.x < 2) {
        double s = 0.0;
        for (int i = 0; i < 16; ++i) s += g_part[threadIdx.x * 16 + i];
        ssc[threadIdx.x] = fmaxf((float)(s / (double)W_ELEMS), 1e-5f);
    }
    __syncthreads();
    int i = blockIdx.x * 256 + threadIdx.x;
    float g = 1.0f / (1.0f + expf(-gate[0]));
    if (i < W_ELEMS) {
        float s1 = ssc[0], s2 = ssc[1];
        float q1 = fminf(fmaxf(rintf(w[i]  / s1), -1.0f), 1.0f) * s1;
        float q2 = fminf(fmaxf(rintf(wc[i] / s2), -1.0f), 1.0f) * s2;
        int o = i / (C_IN * 9);
        int r = i - o * (C_IN * 9);
        int c = r / 9;
        int k = r - c * 9;
        g_wB[k * 4096 + o * 64 + c] = __float2half_rn(q1 + g * q2);
    }
    if (i < C_OUT)
        g_beff[i] = b[i] + g * bc[i];
}

// ---------------------------------------------------------------------------
// Kernel 3: persistent implicit-GEMM conv via HMMA.
//   NEW: QUAD tiles (4 output rows / iteration).  Each warp processes two
//   m32 row-tiles sharing every B fragment -> 8 LDSM per 32 MMA (-33% LDSM).
//   9-slot row ring, advance 4/quad (adjacent) or 6 (image boundary):
//     top:   wait0 + sync  (prev groups landed, all visible)
//     stage 3 rows (slots pos+6..8) -> commit        (group A)
//     compute + epilogue
//     sync   (all reads of ring done)
//     stage 1 row  (slot pos+9==pos) -> commit       (group B)   [adjacent]
//       or  3 rows (slots pos..pos+2)                            [boundary]
// SMEM: B [0,73728) | ring 9 x 16640 [73728,223488) | bias [223488,223744)
// ---------------------------------------------------------------------------
#define AROW_B   16640              // 130*128
#define A_OFF    73728
#define NSLOT    9
#define BIAS_OFF (A_OFF + NSLOT * AROW_B)   // 223488
#define SMEM_CONV (BIAS_OFF + 256)          // 223744
#define NQUADS   512                // 16 images * 32 quads (4 rows each)
#define NCTA     148

// Stage cnt padded rows starting at padded row pr0 into ring slots
// (slotbase+r) % 9.  Source rows contiguous (row stride = AROW_B bytes).
__device__ __forceinline__ void stage_rows(int cnt, int n, int pr0,
                                           int slotbase, uint32_t base, int tid) {
    const char* src = reinterpret_cast<const char*>(
        g_xp + ((size_t)n * HP + pr0) * HP * 64);
    for (int i = tid; i < cnt * 1040; i += 256) {
        int r = i / 1040;
        int k = i - r * 1040;
        int p = k >> 3, j = k & 7;
        int slot = slotbase + r;
        if (slot >= NSLOT) slot -= NSLOT;
        cp16(base + A_OFF + slot * AROW_B + p * 128 + ((j ^ (p & 7)) << 4),
             src + (size_t)r * AROW_B + (size_t)k * 16);
    }
}

__global__ __launch_bounds__(256, 1)
void conv_kernel(float* __restrict__ out) {
    extern __shared__ char sm[];
    const uint32_t base = smem_to_u32(sm);
    const int tid  = threadIdx.x;
    const int wid  = tid >> 5;
    const int lane = tid & 31;

    float* bias_sm = reinterpret_cast<float*>(sm + BIAS_OFF);
    if (tid < 64) bias_sm[tid] = g_beff[tid];

    // Stage all 9 weight tiles (swizzle: chunk j of oc-row nr -> j^(nr&7))
    for (int k = tid; k < 4608; k += 256) {
        int q = k & 511;
        int nr = q >> 3, j = q & 7;
        cp16(base + (k >> 9) * 8192 + nr * 128 + ((j ^ (nr & 7)) << 4),
             reinterpret_cast<const char*>(g_wB) + (size_t)k * 16);
    }

    // Contiguous quad chunk for this CTA
    const int lo = (int)(((long long)blockIdx.x * NQUADS) / NCTA);
    const int hi = (int)(((long long)(blockIdx.x + 1) * NQUADS) / NCTA);

    // Prologue: 6 rows of first quad into slots 0..5 (same group as B)
    stage_rows(6, lo >> 5, (lo & 31) * 4, 0, base, tid);
    cp_commit();
    cp_wait0();
    __syncthreads();

    // Warp layout: rw = row within pair (0/1), m0 = 32-pixel quadrant
    const int rw = wid >> 2;
    const int m0 = (wid & 3) * 32;
    const int a_pl = lane & 15, a_hk = lane >> 4;
    const int b_nl = (lane & 7) + ((lane >> 4) << 3);
    const int b_hk = (lane >> 3) & 1;

    int pos = 0;
    for (int q = lo; q < hi; ++q) {
        const int n  = q >> 5;
        const int y0 = (q & 31) * 4;
        const bool has_next = (q + 1 < hi);
        const bool adj = has_next && ((q & 31) != 31);

        if (q > lo) {               // prev iter's groups landed, make visible
            cp_wait0();
            __syncthreads();
        }
        if (has_next) {             // group A: 3 rows into free slots pos+6..8
            if (adj) {
                stage_rows(3, n, y0 + 6, pos + 6, base, tid);
            } else {
                stage_rows(3, (q + 1) >> 5, ((q + 1) & 31) * 4, pos + 6, base, tid);
            }
            cp_commit();
        }

        float acc[2][2][8][4];      // [tile][mi][nj][reg] = 128 regs
#pragma unroll
        for (int tl = 0; tl < 2; ++tl)
#pragma unroll
            for (int mi = 0; mi < 2; ++mi)
#pragma unroll
                for (int nj = 0; nj < 8; ++nj)
#pragma unroll
                    for (int r = 0; r < 4; ++r) acc[tl][mi][nj][r] = 0.0f;

#pragma unroll
        for (int dy = 0; dy < 3; ++dy) {
            int s0 = pos + rw + dy;     if (s0 >= NSLOT) s0 -= NSLOT;
            int s1 = pos + 2 + rw + dy; if (s1 >= NSLOT) s1 -= NSLOT;
            const uint32_t arow0 = base + A_OFF + s0 * AROW_B;
            const uint32_t arow1 = base + A_OFF + s1 * AROW_B;
#pragma unroll
            for (int dx = 0; dx < 3; ++dx) {
                const uint32_t btap = base + (dy * 3 + dx) * 8192;
#pragma unroll
                for (int kc = 0; kc < 4; ++kc) {
                    uint32_t a0[2][4], a1[2][4];
#pragma unroll
                    for (int mi = 0; mi < 2; ++mi) {
                        int pix = m0 + mi * 16 + a_pl + dx;
                        uint32_t off = pix * 128 +
                            (((2 * kc + a_hk) ^ (pix & 7)) << 4);
                        ldsm_x4(a0[mi], arow0 + off);
                        ldsm_x4(a1[mi], arow1 + off);
                    }
#pragma unroll
                    for (int nj = 0; nj < 4; ++nj) {
                        uint32_t b[4];
                        int nn = nj * 16 + b_nl;
                        ldsm_x4(b, btap + nn * 128 +
                                (((2 * kc + b_hk) ^ (b_nl & 7)) << 4));
#pragma unroll
                        for (int mi = 0; mi < 2; ++mi) {
                            mma16816(acc[0][mi][nj * 2 + 0], a0[mi], b + 0);
                            mma16816(acc[0][mi][nj * 2 + 1], a0[mi], b + 2);
                            mma16816(acc[1][mi][nj * 2 + 0], a1[mi], b + 0);
                            mma16816(acc[1][mi][nj * 2 + 1], a1[mi], b + 2);
                        }
                    }
                }
            }
        }

        // Epilogue: both tiles, STG.32 from fragments, bias from SMEM
        {
            const int pl = lane >> 2, c2 = (lane & 3) * 2;
#pragma unroll
            for (int tl = 0; tl < 2; ++tl) {
                const int y = y0 + 2 * tl + rw;
                float* ob = out + (size_t)n * (64 * 16384) + (size_t)y * 128;
#pragma unroll
                for (int mi = 0; mi < 2; ++mi) {
                    int pbase = m0 + mi * 16 + pl;
#pragma unroll
                    for (int nj = 0; nj < 8; ++nj) {
                        int oc = nj * 8 + c2;
                        float b0 = bias_sm[oc];
                        float b1 = bias_sm[oc + 1];
                        float* p0 = ob + (size_t)oc * 16384;
                        p0[pbase]             = acc[tl][mi][nj][0] + b0;
                        p0[16384 + pbase]     = acc[tl][mi][nj][1] + b1;
                        p0[pbase + 8]         = acc[tl][mi][nj][2] + b0;
                        p0[16384 + pbase + 8] = acc[tl][mi][nj][3] + b1;
                    }
                }
            }
        }

        __syncthreads();            // all warps done reading the ring
        if (has_next) {             // group B into just-freed slots
            if (adj) {
                stage_rows(1, n, y0 + 9, pos + 9, base, tid);
                cp_commit();
                pos += 4; if (pos >= NSLOT) pos -= NSLOT;
            } else {
                stage_rows(3, (q + 1) >> 5, ((q + 1) & 31) * 4 + 3, pos + 9, base, tid);
                cp_commit();
                pos += 6; if (pos >= NSLOT) pos -= NSLOT;
            }
        }
    }
}

// ---------------------------------------------------------------------------
extern "C" void kernel_launch(void* const* d_in, const int* in_sizes, int n_in,
                              void* d_out, int out_size) {
    const float* x  = (const float*)d_in[0];
    const float* w  = (const float*)d_in[1];
    const float* b  = (const float*)d_in[2];
    const float* wc = (const float*)d_in[3];
    const float* bc = (const float*)d_in[4];
    const float* gt = (const float*)d_in[5];
    float* out = (float*)d_out;

    static bool attr_set = false;
    if (!attr_set) {
        cudaFuncSetAttribute(conv_kernel,
                             cudaFuncAttributeMaxDynamicSharedMemorySize, SMEM_CONV);
        attr_set = true;
    }

    transpose_scale_kernel<<<8192 + 32, 256>>>(x, w, wc);
    prep_kernel<<<(W_ELEMS + 255) / 256, 256>>>(w, b, wc, bc, gt);
    conv_kernel<<<NCTA, 256, SMEM_CONV>>>(out);
}

// round 15
// speedup vs baseline: 1.1417x; 1.1417x over previous
#include <cuda_runtime.h>
#include <cuda_fp16.h>
#include <cstdint>

// ---------------------------------------------------------------------------
// Problem constants
// ---------------------------------------------------------------------------
#define N_IMG   16
#define C_IN    64
#define C_OUT   64
#define HH      128
#define WW      128
#define W_ELEMS (C_OUT * C_IN * 9)      // 36864

// ---------------------------------------------------------------------------
// Persistent device scratch
// ---------------------------------------------------------------------------
__device__ double  g_part[32];
__device__ __half  g_wB[9 * 64 * 64];     // [tap][oc][c] fp16 fused weights
__device__ float   g_beff[C_OUT];

// ---------------------------------------------------------------------------
// PTX helpers (sm_103-baseline: cp.async, ldmatrix, mma.sync)
// ---------------------------------------------------------------------------
__device__ __forceinline__ uint32_t smem_to_u32(const void* p) {
    uint32_t a;
    asm("{ .reg .u64 t; cvta.to.shared.u64 t, %1; cvt.u32.u64 %0, t; }"
        : "=r"(a) : "l"(p));
    return a;
}
__device__ __forceinline__ void cp16(uint32_t dst, const void* src) {
    asm volatile("cp.async.cg.shared.global [%0], [%1], 16;" :: "r"(dst), "l"(src));
}
__device__ __forceinline__ void cp_commit() {
    asm volatile("cp.async.commit_group;" ::: "memory");
}
__device__ __forceinline__ void cp_wait0() {
    asm volatile("cp.async.wait_group 0;" ::: "memory");
}
__device__ __forceinline__ void ldsm_x4(uint32_t* r, uint32_t addr) {
    asm volatile("ldmatrix.sync.aligned.m8n8.x4.shared.b16 {%0,%1,%2,%3}, [%4];"
        : "=r"(r[0]), "=r"(r[1]), "=r"(r[2]), "=r"(r[3]) : "r"(addr));
}
__device__ __forceinline__ void mma16816(float* d, const uint32_t* a, const uint32_t* b) {
    asm volatile(
        "mma.sync.aligned.m16n8k16.row.col.f32.f16.f16.f32 "
        "{%0,%1,%2,%3}, {%4,%5,%6,%7}, {%8,%9}, {%0,%1,%2,%3};"
        : "+f"(d[0]), "+f"(d[1]), "+f"(d[2]), "+f"(d[3])
        : "r"(a[0]), "r"(a[1]), "r"(a[2]), "r"(a[3]), "r"(b[0]), "r"(b[1]));
}
__device__ __forceinline__ float4 ldg_cs_f4(const float* p) {
    float4 v;
    asm volatile("ld.global.cs.v4.f32 {%0,%1,%2,%3}, [%4];"
        : "=f"(v.x), "=f"(v.y), "=f"(v.z), "=f"(v.w) : "l"(p));
    return v;
}
__device__ __forceinline__ void sts128(uint32_t addr, uint32_t r0, uint32_t r1,
                                       uint32_t r2, uint32_t r3) {
    asm volatile("st.shared.v4.b32 [%0], {%1,%2,%3,%4};"
        :: "r"(addr), "r"(r0), "r"(r1), "r"(r2), "r"(r3) : "memory");
}
__device__ __forceinline__ uint32_t packh2(float a, float b) {
    __half2 h = __floats2half2_rn(a, b);     // lo=a, hi=b
    return *reinterpret_cast<uint32_t*>(&h);
}

// ---------------------------------------------------------------------------
// Kernel 1: fp64 |w| partial sums (32 blocks)
// ---------------------------------------------------------------------------
__global__ void scale_part_kernel(const float* __restrict__ w,
                                  const float* __restrict__ wc) {
    int b = blockIdx.x;
    const float* p = (b < 16) ? w : wc;
    int seg = b & 15;
    int start = seg * (W_ELEMS / 16);
    double s = 0.0;
    for (int i = start + threadIdx.x; i < start + W_ELEMS / 16; i += 256)
        s += (double)fabsf(p[i]);
    __shared__ double red[256];
    red[threadIdx.x] = s;
    __syncthreads();
    for (int off = 128; off > 0; off >>= 1) {
        if (threadIdx.x < off) red[threadIdx.x] += red[threadIdx.x + off];
        __syncthreads();
    }
    if (threadIdx.x == 0) g_part[b] = red[0];
}

// ---------------------------------------------------------------------------
// Kernel 2: finalize scales (redundant per block) + fuse ternary weights
// ---------------------------------------------------------------------------
__global__ void prep_kernel(const float* __restrict__ w,
                            const float* __restrict__ b,
                            const float* __restrict__ wc,
                            const float* __restrict__ bc,
                            const float* __restrict__ gate) {
    __shared__ float ssc[2];
    if (threadIdx.x < 2) {
        double s = 0.0;
        for (int i = 0; i < 16; ++i) s += g_part[threadIdx.x * 16 + i];
        ssc[threadIdx.x] = fmaxf((float)(s / (double)W_ELEMS), 1e-5f);
    }
    __syncthreads();
    int i = blockIdx.x * 256 + threadIdx.x;
    float g = 1.0f / (1.0f + expf(-gate[0]));
    if (i < W_ELEMS) {
        float s1 = ssc[0], s2 = ssc[1];
        float q1 = fminf(fmaxf(rintf(w[i]  / s1), -1.0f), 1.0f) * s1;
        float q2 = fminf(fmaxf(rintf(wc[i] / s2), -1.0f), 1.0f) * s2;
        int o = i / (C_IN * 9);
        int r = i - o * (C_IN * 9);
        int c = r / 9;
        int k = r - c * 9;
        g_wB[k * 4096 + o * 64 + c] = __float2half_rn(q1 + g * q2);
    }
    if (i < C_OUT)
        g_beff[i] = b[i] + g * bc[i];
}

// ---------------------------------------------------------------------------
// Kernel 3: persistent implicit-GEMM conv via HMMA with FUSED transpose.
//   Mainloop/fragments = round-12 proven config (256 thr, m32n64, full
//   unroll, direct epilogue, 8-slot ring, one sync/tile).  Staging now
//   reads x (NCHW fp32) directly: warp w covers channel octet 8w..8w+7;
//   lane l loads px 4l..4l+3 per channel (coalesced 512B/row), converts
//   RN to fp16, repacks via byte_perm, STS.128 into the IDENTICAL swizzled
//   [px][c] slot layout.  LDG latency hidden under dy0/dy1 compute.
// SMEM: B [0,73728) | A ring 8 x 16640 [73728, 206848)
// ---------------------------------------------------------------------------
#define AROW_B   16640              // 130*128
#define A_OFF    73728
#define SMEM_CONV 206848
#define NTILES2  1024               // 16 images * 64 row-pairs
#define NCTA     148

// Issue 8 coalesced LDG.128 for padded row pr (gy = pr-1) of image n.
// valid=false for the zero rows (pr==0 or pr==129) — no loads issued.
__device__ __forceinline__ bool ldg_row(float4* v, const float* __restrict__ x,
                                        int n, int pr, int w, int l) {
    int gy = pr - 1;
    bool valid = (gy >= 0) && (gy < HH);
    if (valid) {
        const float* rowp = x + ((size_t)(n * 64 + 8 * w) * HH + gy) * WW + 4 * l;
#pragma unroll
        for (int k = 0; k < 8; ++k)
            v[k] = ldg_cs_f4(rowp + (size_t)k * (HH * WW));
    }
    return valid;
}

// Convert + repack + STS.128 one padded row into ring slot (swizzled layout).
__device__ __forceinline__ void sts_row(uint32_t slot, const float4* v,
                                        bool valid, int w, int l) {
    uint32_t h[8][2];
#pragma unroll
    for (int k = 0; k < 8; ++k) {
        h[k][0] = valid ? packh2(v[k].x, v[k].y) : 0u;
        h[k][1] = valid ? packh2(v[k].z, v[k].w) : 0u;
    }
#pragma unroll
    for (int i = 0; i < 4; ++i) {
        const int idx = i >> 1;
        const uint32_t sel = (i & 1) ? 0x7632u : 0x5410u;
        uint32_t r0 = __byte_perm(h[0][idx], h[1][idx], sel);
        uint32_t r1 = __byte_perm(h[2][idx], h[3][idx], sel);
        uint32_t r2 = __byte_perm(h[4][idx], h[5][idx], sel);
        uint32_t r3 = __byte_perm(h[6][idx], h[7][idx], sel);
        int pix = 4 * l + i + 1;          // interior px 1..128
        sts128(slot + pix * 128 + ((w ^ (pix & 7)) << 4), r0, r1, r2, r3);
    }
}

__global__ __launch_bounds__(256, 1)
void conv_kernel(const float* __restrict__ x, float* __restrict__ out) {
    extern __shared__ char sm[];
    const uint32_t base = smem_to_u32(sm);
    const int tid  = threadIdx.x;
    const int wid  = tid >> 5;
    const int lane = tid & 31;

    // Stage all 9 weight tiles (swizzle: chunk j of oc-row nr -> j^(nr&7))
    for (int k = tid; k < 4608; k += 256) {
        int q = k & 511;
        int nr = q >> 3, j = q & 7;
        cp16(base + (k >> 9) * 8192 + nr * 128 + ((j ^ (nr & 7)) << 4),
             reinterpret_cast<const char*>(g_wB) + (size_t)k * 16);
    }
    cp_commit();

    // Zero the entire A ring once (pad columns px0/px129 stay 0 forever)
    for (int i = tid; i < (8 * AROW_B) / 16; i += 256)
        sts128(base + A_OFF + i * 16, 0u, 0u, 0u, 0u);
    __syncthreads();

    // Contiguous tile chunk for this CTA
    const int lo = (int)(((long long)blockIdx.x * NTILES2) / NCTA);
    const int hi = (int)(((long long)(blockIdx.x + 1) * NTILES2) / NCTA);

    // Prologue: 4 rows of first tile into slots 0..3 (direct from x)
    {
        const int n0 = lo >> 6, y0 = (lo & 63) * 2;
#pragma unroll 1
        for (int r = 0; r < 4; ++r) {
            float4 v[8];
            bool ok = ldg_row(v, x, n0, y0 + r, wid, lane);
            sts_row(base + A_OFF + r * AROW_B, v, ok, wid, lane);
        }
    }
    cp_wait0();                      // B resident
    __syncthreads();                 // A prologue + B visible

    // Warp layout: rw = output row within pair, m0 = 32-pixel quadrant
    const int rw = wid >> 2;
    const int m0 = (wid & 3) * 32;
    const int a_pl = lane & 15, a_hk = lane >> 4;
    const int b_nl = (lane & 7) + ((lane >> 4) << 3);
    const int b_hk = (lane >> 3) & 1;

    // Per-thread bias registers: oc = nj*8 + (lane&3)*2 + {0,1}
    float bv[8][2];
#pragma unroll
    for (int nj = 0; nj < 8; ++nj) {
        bv[nj][0] = g_beff[nj * 8 + (lane & 3) * 2];
        bv[nj][1] = g_beff[nj * 8 + (lane & 3) * 2 + 1];
    }

    int pos = 0;
    for (int t = lo; t < hi; ++t) {
        const bool has_next = (t + 1 < hi);
        const int nn  = (t + 1) >> 6;
        const int y0n = ((t + 1) & 63) * 2;
        const bool adj = has_next && (nn == (t >> 6));
        // rows to stage for next tile: adjacent -> padded rows y0n+2, y0n+3
        //                              boundary -> y0n .. y0n+3 (new image)
        const int pr0 = adj ? y0n + 2 : y0n;
        const int pr1 = pr0 + 1;

        float acc[2][8][4];
#pragma unroll
        for (int mi = 0; mi < 2; ++mi)
#pragma unroll
            for (int nj = 0; nj < 8; ++nj)
#pragma unroll
                for (int r = 0; r < 4; ++r) acc[mi][nj][r] = 0.0f;

        // dy body (dx/kc fully unrolled; dy passed as runtime arg)
        auto dy_body = [&](int dy) {
            const uint32_t arow = base + A_OFF +
                ((pos + rw + dy) & 7) * AROW_B;
#pragma unroll
            for (int dx = 0; dx < 3; ++dx) {
                const uint32_t btap = base + (dy * 3 + dx) * 8192;
#pragma unroll
                for (int kc = 0; kc < 4; ++kc) {
                    uint32_t a[2][4];
#pragma unroll
                    for (int mi = 0; mi < 2; ++mi) {
                        int pix = m0 + mi * 16 + a_pl + dx;
                        ldsm_x4(a[mi], arow + pix * 128 +
                                (((2 * kc + a_hk) ^ (pix & 7)) << 4));
                    }
#pragma unroll
                    for (int nj = 0; nj < 4; ++nj) {
                        uint32_t b[4];
                        int nb = nj * 16 + b_nl;
                        ldsm_x4(b, btap + nb * 128 +
                                (((2 * kc + b_hk) ^ (b_nl & 7)) << 4));
#pragma unroll
                        for (int mi = 0; mi < 2; ++mi) {
                            mma16816(acc[mi][nj * 2 + 0], a[mi], b + 0);
                            mma16816(acc[mi][nj * 2 + 1], a[mi], b + 2);
                        }
                    }
                }
            }
        };

        // Interleaved staging: LDG row0 -> dy0 -> STS row0 ->
        //                      LDG row1 -> dy1 -> STS row1 -> dy2
        {
            float4 va[8];
            bool oka = false;
            if (has_next) oka = ldg_row(va, x, nn, pr0, wid, lane);
            dy_body(0);
            if (has_next)
                sts_row(base + A_OFF + ((pos + 4) & 7) * AROW_B, va, oka, wid, lane);
        }
        {
            float4 vb[8];
            bool okb = false;
            if (has_next) okb = ldg_row(vb, x, nn, pr1, wid, lane);
            dy_body(1);
            if (has_next)
                sts_row(base + A_OFF + ((pos + 5) & 7) * AROW_B, vb, okb, wid, lane);
        }
        dy_body(2);

        // Direct epilogue: STG.32 from fragments, bias fused in registers
        {
            const int n = t >> 6, y = (t & 63) * 2 + rw;
            float* ob = out + (size_t)n * (64 * 16384) + (size_t)y * 128;
            const int pl = lane >> 2;
#pragma unroll
            for (int mi = 0; mi < 2; ++mi) {
                int pbase = m0 + mi * 16 + pl;
#pragma unroll
                for (int nj = 0; nj < 8; ++nj) {
                    float* p0 = ob + (size_t)(nj * 8 + (lane & 3) * 2) * 16384;
                    p0[pbase]             = acc[mi][nj][0] + bv[nj][0];
                    p0[16384 + pbase]     = acc[mi][nj][1] + bv[nj][1];
                    p0[pbase + 8]         = acc[mi][nj][2] + bv[nj][0];
                    p0[16384 + pbase + 8] = acc[mi][nj][3] + bv[nj][1];
                }
            }
        }

        // Image boundary: stage the remaining 2 rows of the new image
        if (has_next && !adj) {
#pragma unroll 1
            for (int r = 2; r < 4; ++r) {
                float4 v[8];
                bool ok = ldg_row(v, x, nn, y0n + r, wid, lane);
                sts_row(base + A_OFF + ((pos + 4 + r) & 7) * AROW_B, v, ok, wid, lane);
            }
        }

        __syncthreads();             // staged rows visible; ring reads done
        if (has_next) pos = (pos + (adj ? 2 : 4)) & 7;
    }
}

// ---------------------------------------------------------------------------
extern "C" void kernel_launch(void* const* d_in, const int* in_sizes, int n_in,
                              void* d_out, int out_size) {
    const float* x  = (const float*)d_in[0];
    const float* w  = (const float*)d_in[1];
    const float* b  = (const float*)d_in[2];
    const float* wc = (const float*)d_in[3];
    const float* bc = (const float*)d_in[4];
    const float* gt = (const float*)d_in[5];
    float* out = (float*)d_out;

    static bool attr_set = false;
    if (!attr_set) {
        cudaFuncSetAttribute(conv_kernel,
                             cudaFuncAttributeMaxDynamicSharedMemorySize, SMEM_CONV);
        attr_set = true;
    }

    scale_part_kernel<<<32, 256>>>(w, wc);
    prep_kernel<<<(W_ELEMS + 255) / 256, 256>>>(w, b, wc, bc, gt);
    conv_kernel<<<NCTA, 256, SMEM_CONV>>>(x, out);
}